// round 2
// baseline (speedup 1.0000x reference)
#include <cuda_runtime.h>
#include <math.h>

#define BB 4
#define SS 2048
#define DD 1024
#define HH 16
#define BD (BB*DD)          // 4096
#define MT (BB*SS)          // 8192
#define CH 128
#define NC (SS/CH)          // 16

#define RP   128            // persistent CTAs in recurrence
#define RR   (DD/RP)        // 8 rows per CTA

// ------------------------- scratch (device globals; no allocation) ---------
__device__ float g_ret[(size_t)MT*DD];
__device__ float g_inp[(size_t)MT*DD];
__device__ float g_gl [(size_t)MT*DD];
__device__ float g_ct [(size_t)MT*DD];
__device__ float g_st [(size_t)MT*DD];
__device__ float g_chend[BD*NC];
__device__ float g_carry[BD*NC];
__device__ float g_blend[2*BD];
__device__ unsigned g_bar;

// ------------------------- misc ---------------------------------------------
__global__ void k_reset() { g_bar = 0u; }

// ------------------------- retention scan (chunked parallel scan) ----------
// pass 1: per (b, chunk, d) compute chunk-local end value of r (carry-in 0)
__global__ void k_scan1(const float* __restrict__ k, const float* __restrict__ v,
                        const float* __restrict__ decay)
{
    int g = blockIdx.x * blockDim.x + threadIdx.x;     // 65536 threads
    int d    = g & (DD-1);
    int rest = g >> 10;
    int ch   = rest & (NC-1);
    int b    = rest >> 4;
    float dec = decay[d >> 6];
    size_t base = ((size_t)(b*SS + ch*CH))*DD + d;
    float r = 0.f;
#pragma unroll 4
    for (int t = 0; t < CH; t++) {
        r = dec*r + k[base + (size_t)t*DD] * v[base + (size_t)t*DD];
    }
    g_chend[(b*NC + ch)*DD + d] = r;
}

// pass 2: per (b, d) scan across the 16 chunks -> carry-in per chunk
__global__ void k_scan2(const float* __restrict__ decay)
{
    int g = blockIdx.x * blockDim.x + threadIdx.x;     // 4096 threads
    int d = g & (DD-1);
    int b = g >> 10;
    float dec = decay[d >> 6];
    float dL = dec;
#pragma unroll
    for (int i = 0; i < 7; i++) dL *= dL;              // dec^128
    float r = 0.f;
#pragma unroll
    for (int ch = 0; ch < NC; ch++) {
        g_carry[(b*NC + ch)*DD + d] = r;
        r = g_chend[(b*NC + ch)*DD + d] + dL * r;
    }
}

// pass 3: recompute local scan with carry, write retained = q * r
__global__ void k_scan3(const float* __restrict__ q, const float* __restrict__ k,
                        const float* __restrict__ v, const float* __restrict__ decay)
{
    int g = blockIdx.x * blockDim.x + threadIdx.x;     // 65536 threads
    int d    = g & (DD-1);
    int rest = g >> 10;
    int ch   = rest & (NC-1);
    int b    = rest >> 4;
    float dec = decay[d >> 6];
    float r = g_carry[(b*NC + ch)*DD + d];
    size_t base = ((size_t)(b*SS + ch*CH))*DD + d;
#pragma unroll 4
    for (int t = 0; t < CH; t++) {
        size_t o = base + (size_t)t*DD;
        r = dec*r + k[o]*v[o];
        g_ret[o] = q[o]*r;
    }
}

// ------------------------- fp32 SIMT GEMM:  C[M,N] = Act[M,K] @ W[N,K]^T (+bias)
__global__ __launch_bounds__(256, 2)
void k_gemm(const float* __restrict__ A, const float* __restrict__ W,
            const float* __restrict__ bias, float* __restrict__ C,
            int M, int N, int K, int hasBias)
{
    __shared__ float As[16][128];
    __shared__ float Bs[16][128];
    int tid = threadIdx.x;
    const float* Ab = A + (size_t)blockIdx.y * 128 * K;
    const float* Wb = W + (size_t)blockIdx.x * 128 * K;

    float acc[8][8];
#pragma unroll
    for (int m = 0; m < 8; m++)
#pragma unroll
        for (int n = 0; n < 8; n++) acc[m][n] = 0.f;

    int tr = tid >> 4, tc = tid & 15;   // 16x16 threads, 8x8 microtile each

    for (int k0 = 0; k0 < K; k0 += 16) {
#pragma unroll
        for (int i = 0; i < 2; i++) {
            int f   = tid + i*256;          // 512 float4 per operand tile
            int row = f >> 2;
            int c4  = (f & 3) * 4;
            float4 va = *(const float4*)(Ab + (size_t)row*K + k0 + c4);
            As[c4+0][row] = va.x; As[c4+1][row] = va.y;
            As[c4+2][row] = va.z; As[c4+3][row] = va.w;
            float4 vb = *(const float4*)(Wb + (size_t)row*K + k0 + c4);
            Bs[c4+0][row] = vb.x; Bs[c4+1][row] = vb.y;
            Bs[c4+2][row] = vb.z; Bs[c4+3][row] = vb.w;
        }
        __syncthreads();
#pragma unroll
        for (int kk = 0; kk < 16; kk++) {
            float ra[8], rb[8];
            *(float4*)(ra)   = *(const float4*)&As[kk][tr*8];
            *(float4*)(ra+4) = *(const float4*)&As[kk][tr*8+4];
            *(float4*)(rb)   = *(const float4*)&Bs[kk][tc*8];
            *(float4*)(rb+4) = *(const float4*)&Bs[kk][tc*8+4];
#pragma unroll
            for (int m = 0; m < 8; m++)
#pragma unroll
                for (int n = 0; n < 8; n++)
                    acc[m][n] = fmaf(ra[m], rb[n], acc[m][n]);
        }
        __syncthreads();
    }

    int mbase = blockIdx.y*128 + tr*8;
    int nbase = blockIdx.x*128 + tc*8;
#pragma unroll
    for (int m = 0; m < 8; m++) {
#pragma unroll
        for (int n4 = 0; n4 < 2; n4++) {
            float4 o;
            o.x = acc[m][n4*4+0]; o.y = acc[m][n4*4+1];
            o.z = acc[m][n4*4+2]; o.w = acc[m][n4*4+3];
            if (hasBias) {
                o.x += bias[nbase+n4*4+0]; o.y += bias[nbase+n4*4+1];
                o.z += bias[nbase+n4*4+2]; o.w += bias[nbase+n4*4+3];
            }
            *(float4*)(C + (size_t)(mbase+m)*N + nbase + n4*4) = o;
        }
    }
}

// ------------------------- sequential state recurrence ----------------------
// Persistent kernel, RP CTAs (one per SM, all co-resident). CTA i owns output
// dims [i*RR, i*RR+RR). A rows kept in registers (128 floats/thread).
// Per step: compute blended slice locally -> publish -> grid barrier ->
// stage full blended (16KB) in SMEM -> register-A GEMV -> tanh -> state.
__global__ __launch_bounds__(256, 1)
void k_recur(const float* __restrict__ Amat)
{
    __shared__ float bl_s[4][1032];   // padded: conflict-free broadcast
    __shared__ float part[8][32];
    __shared__ float st_s[32];

    int tid  = threadIdx.x;
    int cta  = blockIdx.x;
    int row0 = cta * RR;
    int w    = tid >> 5;              // warp = k-chunk of 128
    int lane = tid & 31;
    int lr   = lane >> 2;             // local row 0..7
    int bo   = lane & 3;              // batch 0..3

    // A slice into registers: A[row0+lr][w*128 .. w*128+127]
    float4 a4[32];
    {
        const float* Arow = Amat + (size_t)(row0 + lr)*DD + w*128;
#pragma unroll
        for (int i = 0; i < 32; i++) a4[i] = *(const float4*)(Arow + i*4);
    }
    if (tid < 32) st_s[tid] = 0.f;
    __syncthreads();

    for (int t = 0; t < SS; t++) {
        // 1) blended slice: bl = inp + gate*(state - inp)
        if (tid < 32) {
            int l2 = tid >> 2, b2 = tid & 3;
            size_t gi = ((size_t)(b2*SS + t))*DD + row0 + l2;
            float glv = g_gl[gi];
            float ip  = g_inp[gi];
            float gate = 1.f / (1.f + expf(-glv));
            float bl = fmaf(gate, st_s[tid] - ip, ip);
            g_blend[(t & 1)*BD + b2*DD + row0 + l2] = bl;
        }
        __syncthreads();

        // 2) grid barrier (counting, reset by k_reset each launch)
        if (tid == 0) {
            __threadfence();
            atomicAdd(&g_bar, 1u);
            unsigned target = (unsigned)(t + 1) * RP;
            while (*(volatile unsigned*)&g_bar < target) { __nanosleep(32); }
            __threadfence();
        }
        __syncthreads();

        // 3) stage full blended vector into SMEM (bypass L1: buffer reused)
        {
            const float4* src = (const float4*)(g_blend + (t & 1)*BD);
#pragma unroll
            for (int i = 0; i < 4; i++) {
                int idx = tid + i*256;            // 1024 float4
                float4 vv = __ldcg(src + idx);
                int b2 = idx >> 8;
                int k4 = (idx & 255) * 4;
                *(float4*)&bl_s[b2][k4] = vv;
            }
        }
        __syncthreads();

        // 4) register-A GEMV over this warp's k-chunk
        {
            const float4* xb = (const float4*)&bl_s[bo][w*128];
            float s0 = 0.f, s1 = 0.f, s2 = 0.f, s3 = 0.f;
#pragma unroll
            for (int i = 0; i < 32; i++) {
                float4 x = xb[i];
                s0 = fmaf(a4[i].x, x.x, s0);
                s1 = fmaf(a4[i].y, x.y, s1);
                s2 = fmaf(a4[i].z, x.z, s2);
                s3 = fmaf(a4[i].w, x.w, s3);
            }
            part[w][lane] = (s0 + s1) + (s2 + s3);
        }
        __syncthreads();

        // 5) reduce 8 k-chunks, add Bm-term, tanh, commit state
        if (tid < 32) {
            float s = 0.f;
#pragma unroll
            for (int ww = 0; ww < 8; ww++) s += part[ww][tid];
            int l2 = tid >> 2, b2 = tid & 3;
            size_t gi = ((size_t)(b2*SS + t))*DD + row0 + l2;
            float ns = tanhf(s + g_ct[gi]);
            st_s[tid] = ns;
            g_st[gi] = ns;
        }
        __syncthreads();
    }
}

// ------------------------- launch -------------------------------------------
extern "C" void kernel_launch(void* const* d_in, const int* in_sizes, int n_in,
                              void* d_out, int out_size)
{
    const float* q     = (const float*)d_in[0];
    const float* k     = (const float*)d_in[1];
    const float* v     = (const float*)d_in[2];
    const float* Wi    = (const float*)d_in[3];
    const float* bi    = (const float*)d_in[4];
    const float* Wg    = (const float*)d_in[5];
    const float* bg    = (const float*)d_in[6];
    const float* A     = (const float*)d_in[7];
    const float* Bm    = (const float*)d_in[8];
    const float* Wo    = (const float*)d_in[9];
    const float* bo    = (const float*)d_in[10];
    const float* decay = (const float*)d_in[11];
    float* out = (float*)d_out;

    void *p_ret, *p_inp, *p_gl, *p_ct, *p_st;
    cudaGetSymbolAddress(&p_ret, g_ret);
    cudaGetSymbolAddress(&p_inp, g_inp);
    cudaGetSymbolAddress(&p_gl,  g_gl);
    cudaGetSymbolAddress(&p_ct,  g_ct);
    cudaGetSymbolAddress(&p_st,  g_st);

    k_reset<<<1, 1>>>();

    k_scan1<<<(BD*NC)/256, 256>>>(k, v, decay);
    k_scan2<<<BD/256, 256>>>(decay);
    k_scan3<<<(BD*NC)/256, 256>>>(q, k, v, decay);

    dim3 gg(DD/128, MT/128);   // (N tiles, M tiles)
    // inp = retained @ Wi.T + bi
    k_gemm<<<gg, 256>>>((const float*)p_ret, Wi, bi, (float*)p_inp, MT, DD, DD, 1);
    // gate logits = inp @ Wg.T + bg
    k_gemm<<<gg, 256>>>((const float*)p_inp, Wg, bg, (float*)p_gl, MT, DD, DD, 1);
    // ct = inp @ Bm.T
    k_gemm<<<gg, 256>>>((const float*)p_inp, Bm, (const float*)0, (float*)p_ct, MT, DD, DD, 0);

    // sequential recurrence over S steps
    k_recur<<<RP, 256>>>(A);

    // out = state @ Wo.T + bo
    k_gemm<<<gg, 256>>>((const float*)p_st, Wo, bo, out, MT, DD, DD, 1);
}